// round 1
// baseline (speedup 1.0000x reference)
#include <cuda_runtime.h>
#include <cstdint>
#include <cstddef>

// ---------------------------------------------------------------------------
// SpatialSelfAttention: GroupNorm(32) -> QKV 1x1 conv -> full softmax
// attention over N=4096 positions (single head, d=512) -> O proj + residual.
// Round 0: fp32 SIMT tiled GEMM engine (128x128x8, 8x8 microtile).
// ---------------------------------------------------------------------------

namespace {
constexpr int kB = 8;
constexpr int kC = 512;
constexpr int kN = 4096;          // H*W
constexpr int kG = 32;            // groups
constexpr int kCPG = kC / kG;     // 16 channels per group
constexpr size_t kCN = (size_t)kC * kN;   // 2,097,152
constexpr size_t kNN = (size_t)kN * kN;   // 16,777,216
}

// Scratch (allocation-free rule: __device__ globals)
__device__ float g_hn[kB * kCN];   // 64 MB  groupnorm output
__device__ float g_q [kB * kCN];   // 64 MB
__device__ float g_k [kB * kCN];   // 64 MB
__device__ float g_v [kB * kCN];   // 64 MB
__device__ float g_o [kB * kCN];   // 64 MB  attn @ V
__device__ float g_s [kB * kNN];   // 512 MB scores / probs

// ---------------------------------------------------------------------------
// GroupNorm: one block per (batch, group). 16 ch x 4096 = 65536 elements.
// ---------------------------------------------------------------------------
__global__ __launch_bounds__(256) void gn_kernel(const float* __restrict__ x,
                                                 const float* __restrict__ scale,
                                                 const float* __restrict__ bias,
                                                 float* __restrict__ hn) {
    const int b = blockIdx.x / kG;
    const int g = blockIdx.x % kG;
    const size_t base = (size_t)b * kCN + (size_t)g * kCPG * kN;
    const float4* x4 = reinterpret_cast<const float4*>(x + base);
    float4* hn4 = reinterpret_cast<float4*>(hn + base);
    const int nvec = kCPG * kN / 4;  // 16384 float4s

    float s = 0.f, ss = 0.f;
    for (int i = threadIdx.x; i < nvec; i += 256) {
        float4 v = x4[i];
        s  += v.x + v.y + v.z + v.w;
        ss += v.x * v.x + v.y * v.y + v.z * v.z + v.w * v.w;
    }
    __shared__ float smS[8], smSS[8];
    #pragma unroll
    for (int o = 16; o > 0; o >>= 1) {
        s  += __shfl_xor_sync(0xffffffffu, s, o);
        ss += __shfl_xor_sync(0xffffffffu, ss, o);
    }
    if ((threadIdx.x & 31) == 0) {
        smS [threadIdx.x >> 5] = s;
        smSS[threadIdx.x >> 5] = ss;
    }
    __syncthreads();
    float S = 0.f, SS = 0.f;
    #pragma unroll
    for (int i = 0; i < 8; i++) { S += smS[i]; SS += smSS[i]; }

    const float invn = 1.f / (float)(kCPG * kN);
    const float mean = S * invn;
    const float var  = SS * invn - mean * mean;
    const float inv  = rsqrtf(var + 1e-6f);

    for (int i = threadIdx.x; i < nvec; i += 256) {
        const int cl = i / (kN / 4);           // local channel 0..15
        const int c  = g * kCPG + cl;
        const float sc = scale[c] * inv;
        const float bi = bias[c] - mean * sc;
        float4 v = x4[i];
        float4 r;
        r.x = v.x * sc + bi; r.y = v.y * sc + bi;
        r.z = v.z * sc + bi; r.w = v.w * sc + bi;
        hn4[i] = r;
    }
}

// ---------------------------------------------------------------------------
// Generic fp32 tiled GEMM: C = alpha * op(A) @ op(B) [+ bias[m]] [+ resid]
//   !TA: A is [M,K] row-major (elem(m,k) = A[m*lda+k])
//    TA: A stored [K,M]       (elem(m,k) = A[k*lda+m])
//   !TB: B is [K,N] row-major (elem(k,n) = B[k*ldb+n])
//    TB: B stored [N,K]       (elem(k,n) = B[n*ldb+k])
// All dims must be multiples of 128 (M,N) and 8 (K) — true for this problem.
// blockIdx.z = batch; per-batch strides sA/sB/sC/sR (0 for shared weights).
// ---------------------------------------------------------------------------
template <bool TA, bool TB>
__global__ __launch_bounds__(256) void gemm_kernel(
    const float* __restrict__ A, int lda, size_t sA,
    const float* __restrict__ Bm, int ldb, size_t sB,
    float* __restrict__ Cm, int ldc, size_t sC,
    int M, int N, int K, float alpha,
    const float* __restrict__ bias,
    const float* __restrict__ resid, size_t sR)
{
    constexpr int BM = 128, BN = 128, BK = 8;
    A  += (size_t)blockIdx.z * sA;
    Bm += (size_t)blockIdx.z * sB;
    Cm += (size_t)blockIdx.z * sC;
    if (resid) resid += (size_t)blockIdx.z * sR;

    const int bm = blockIdx.y * BM;
    const int bn = blockIdx.x * BN;

    __shared__ __align__(16) float As[BK][BM];
    __shared__ __align__(16) float Bs[BK][BN];

    const int tid = threadIdx.x;
    const int tx = tid & 15;       // 0..15 -> 8 cols each
    const int ty = tid >> 4;       // 0..15 -> 8 rows each

    float acc[8][8];
    #pragma unroll
    for (int i = 0; i < 8; i++)
        #pragma unroll
        for (int j = 0; j < 8; j++) acc[i][j] = 0.f;

    for (int k0 = 0; k0 < K; k0 += BK) {
        #pragma unroll
        for (int i = 0; i < 4; i++) {
            const int li = tid + i * 256;
            if (TA) { const int m = li & 127, k = li >> 7;
                      As[k][m] = A[(size_t)(k0 + k) * lda + (bm + m)]; }
            else    { const int k = li & 7, m = li >> 3;
                      As[k][m] = A[(size_t)(bm + m) * lda + (k0 + k)]; }
            if (TB) { const int k = li & 7, n = li >> 3;
                      Bs[k][n] = Bm[(size_t)(bn + n) * ldb + (k0 + k)]; }
            else    { const int n = li & 127, k = li >> 7;
                      Bs[k][n] = Bm[(size_t)(k0 + k) * ldb + (bn + n)]; }
        }
        __syncthreads();
        #pragma unroll
        for (int kk = 0; kk < BK; kk++) {
            const float4 a0 = *reinterpret_cast<const float4*>(&As[kk][ty * 8]);
            const float4 a1 = *reinterpret_cast<const float4*>(&As[kk][ty * 8 + 4]);
            const float4 b0 = *reinterpret_cast<const float4*>(&Bs[kk][tx * 8]);
            const float4 b1 = *reinterpret_cast<const float4*>(&Bs[kk][tx * 8 + 4]);
            const float a[8]  = {a0.x, a0.y, a0.z, a0.w, a1.x, a1.y, a1.z, a1.w};
            const float bb[8] = {b0.x, b0.y, b0.z, b0.w, b1.x, b1.y, b1.z, b1.w};
            #pragma unroll
            for (int i = 0; i < 8; i++)
                #pragma unroll
                for (int j = 0; j < 8; j++)
                    acc[i][j] += a[i] * bb[j];
        }
        __syncthreads();
    }

    #pragma unroll
    for (int i = 0; i < 8; i++) {
        const int m = bm + ty * 8 + i;
        const float bi = bias ? bias[m] : 0.f;
        #pragma unroll
        for (int j = 0; j < 8; j += 4) {
            const int n = bn + tx * 8 + j;
            float4 r;
            r.x = acc[i][j + 0] * alpha + bi;
            r.y = acc[i][j + 1] * alpha + bi;
            r.z = acc[i][j + 2] * alpha + bi;
            r.w = acc[i][j + 3] * alpha + bi;
            if (resid) {
                const float4 rv = *reinterpret_cast<const float4*>(
                    &resid[(size_t)m * ldc + n]);
                r.x += rv.x; r.y += rv.y; r.z += rv.z; r.w += rv.w;
            }
            *reinterpret_cast<float4*>(&Cm[(size_t)m * ldc + n]) = r;
        }
    }
}

// ---------------------------------------------------------------------------
// In-place row softmax over 4096 keys. block = one row (query i of batch b).
// ---------------------------------------------------------------------------
__global__ __launch_bounds__(256) void softmax_kernel(float* __restrict__ s) {
    float* row = s + ((size_t)blockIdx.y * kN + (size_t)blockIdx.x) * kN;
    float4* row4 = reinterpret_cast<float4*>(row);

    float4 r[4];
    float mx = -3.402823e38f;
    #pragma unroll
    for (int i = 0; i < 4; i++) {
        r[i] = row4[threadIdx.x + i * 256];
        mx = fmaxf(mx, fmaxf(fmaxf(r[i].x, r[i].y), fmaxf(r[i].z, r[i].w)));
    }

    __shared__ float sm[8];
    #pragma unroll
    for (int o = 16; o > 0; o >>= 1)
        mx = fmaxf(mx, __shfl_xor_sync(0xffffffffu, mx, o));
    if ((threadIdx.x & 31) == 0) sm[threadIdx.x >> 5] = mx;
    __syncthreads();
    float m = sm[0];
    #pragma unroll
    for (int i = 1; i < 8; i++) m = fmaxf(m, sm[i]);
    __syncthreads();

    float sum = 0.f;
    #pragma unroll
    for (int i = 0; i < 4; i++) {
        r[i].x = __expf(r[i].x - m); sum += r[i].x;
        r[i].y = __expf(r[i].y - m); sum += r[i].y;
        r[i].z = __expf(r[i].z - m); sum += r[i].z;
        r[i].w = __expf(r[i].w - m); sum += r[i].w;
    }
    #pragma unroll
    for (int o = 16; o > 0; o >>= 1)
        sum += __shfl_xor_sync(0xffffffffu, sum, o);
    if ((threadIdx.x & 31) == 0) sm[threadIdx.x >> 5] = sum;
    __syncthreads();
    float tot = 0.f;
    #pragma unroll
    for (int i = 0; i < 8; i++) tot += sm[i];
    const float inv = 1.f / tot;

    #pragma unroll
    for (int i = 0; i < 4; i++) {
        r[i].x *= inv; r[i].y *= inv; r[i].z *= inv; r[i].w *= inv;
        row4[threadIdx.x + i * 256] = r[i];
    }
}

// ---------------------------------------------------------------------------
extern "C" void kernel_launch(void* const* d_in, const int* in_sizes, int n_in,
                              void* d_out, int out_size) {
    const float* x  = (const float*)d_in[0];
    const float* gs = (const float*)d_in[1];
    const float* gb = (const float*)d_in[2];
    const float* wq = (const float*)d_in[3];
    const float* bq = (const float*)d_in[4];
    const float* wk = (const float*)d_in[5];
    const float* bk = (const float*)d_in[6];
    const float* wv = (const float*)d_in[7];
    const float* bv = (const float*)d_in[8];
    const float* wo = (const float*)d_in[9];
    const float* bo = (const float*)d_in[10];
    float* out = (float*)d_out;

    float *p_hn, *p_q, *p_k, *p_v, *p_o, *p_s;
    cudaGetSymbolAddress((void**)&p_hn, g_hn);
    cudaGetSymbolAddress((void**)&p_q,  g_q);
    cudaGetSymbolAddress((void**)&p_k,  g_k);
    cudaGetSymbolAddress((void**)&p_v,  g_v);
    cudaGetSymbolAddress((void**)&p_o,  g_o);
    cudaGetSymbolAddress((void**)&p_s,  g_s);

    // 1. GroupNorm
    gn_kernel<<<kB * kG, 256>>>(x, gs, gb, p_hn);

    // 2. Q/K/V projections: [512,512] @ [512,4096] per batch
    const dim3 gProj(kN / 128, kC / 128, kB);   // (32, 4, 8)
    gemm_kernel<false, false><<<gProj, 256>>>(
        wq, kC, 0, p_hn, kN, kCN, p_q, kN, kCN, kC, kN, kC, 1.f, bq, nullptr, 0);
    gemm_kernel<false, false><<<gProj, 256>>>(
        wk, kC, 0, p_hn, kN, kCN, p_k, kN, kCN, kC, kN, kC, 1.f, bk, nullptr, 0);
    gemm_kernel<false, false><<<gProj, 256>>>(
        wv, kC, 0, p_hn, kN, kCN, p_v, kN, kCN, kC, kN, kC, 1.f, bv, nullptr, 0);

    // 3. scores = (Q^T K) / sqrt(C): [4096,4096] per batch (TN gemm)
    const dim3 gScore(kN / 128, kN / 128, kB);  // (32, 32, 8)
    gemm_kernel<true, false><<<gScore, 256>>>(
        p_q, kN, kCN, p_k, kN, kCN, p_s, kN, kNN,
        kN, kN, kC, 0.044194173824159216f, nullptr, nullptr, 0);

    // 4. softmax over keys, in place
    softmax_kernel<<<dim3(kN, kB), 256>>>(p_s);

    // 5. attn @ V: O[c,i] = sum_j V[c,j] P[i,j]  (NT gemm)
    gemm_kernel<false, true><<<gProj, 256>>>(
        p_v, kN, kCN, p_s, kN, kNN, p_o, kN, kCN,
        kC, kN, kN, 1.f, nullptr, nullptr, 0);

    // 6. output projection + bias + residual
    gemm_kernel<false, false><<<gProj, 256>>>(
        wo, kC, 0, p_o, kN, kCN, out, kN, kCN,
        kC, kN, kC, 1.f, bo, x, kCN);
}

// round 6
// speedup vs baseline: 4.4054x; 4.4054x over previous
#include <cuda_runtime.h>
#include <cstdint>
#include <cstddef>

// ---------------------------------------------------------------------------
// SpatialSelfAttention on GB300 — tf32 mma.sync tensor-core GEMM engine.
// (tcgen05 is unavailable: harness PTX pass targets compute_103, arch-specific
//  instructions rejected. mma.sync.m16n8k8.tf32 is baseline sm_80 PTX.)
// Layouts: ALL five GEMMs are K-major x K-major:
//   hn_T, q_t, k_t, oT : [n_spatial, c]
//   v, scores, out     : [c or i, 4096]
// ---------------------------------------------------------------------------

namespace {
constexpr int kB = 8;
constexpr int kC = 512;
constexpr int kN = 4096;
constexpr int kG = 32;
constexpr int kCPG = kC / kG;
constexpr size_t kCN = (size_t)kC * kN;
constexpr size_t kNN = (size_t)kN * kN;
constexpr int kSmemBytes = 2 * 32768;   // double-buffered A+B tiles
}

// Scratch
__device__ float g_hn [kB * kCN];
__device__ float g_hnT[kB * kCN];
__device__ float g_qT [kB * kCN];
__device__ float g_kT [kB * kCN];
__device__ float g_v  [kB * kCN];
__device__ float g_oT [kB * kCN];
__device__ float g_s  [kB * kNN];
__device__ float g_wr [4 * kC * kC];

// ---------------------------------------------------------------------------
__device__ __forceinline__ uint32_t smem_u32(const void* p) {
    uint32_t a;
    asm("{ .reg .u64 t; cvta.to.shared.u64 t, %1; cvt.u32.u64 %0, t; }"
        : "=r"(a) : "l"(p));
    return a;
}
__device__ __forceinline__ float to_tf32(float x) {
    uint32_t u;
    asm("cvt.rna.tf32.f32 %0, %1;" : "=r"(u) : "f"(x));
    return __uint_as_float(u);
}
__device__ __forceinline__ void cp_async16(uint32_t dst, const void* src) {
    asm volatile("cp.async.cg.shared.global [%0], [%1], 16;"
                 :: "r"(dst), "l"(src));
}
__device__ __forceinline__ void ldsm_x4(uint32_t* r, uint32_t addr) {
    asm volatile("ldmatrix.sync.aligned.m8n8.x4.shared.b16 {%0,%1,%2,%3}, [%4];"
                 : "=r"(r[0]), "=r"(r[1]), "=r"(r[2]), "=r"(r[3]) : "r"(addr));
}
__device__ __forceinline__ void mma_tf32(float* d, const uint32_t* a,
                                         const uint32_t* b) {
    asm volatile(
        "mma.sync.aligned.m16n8k8.row.col.f32.tf32.tf32.f32 "
        "{%0,%1,%2,%3}, {%4,%5,%6,%7}, {%8,%9}, {%0,%1,%2,%3};"
        : "+f"(d[0]), "+f"(d[1]), "+f"(d[2]), "+f"(d[3])
        : "r"(a[0]), "r"(a[1]), "r"(a[2]), "r"(a[3]), "r"(b[0]), "r"(b[1]));
}

// ---------------------------------------------------------------------------
// tf32 GEMM: D[m,n] = alpha * sum_k A[m,k]*B[n,k] (+bias)(+resid)
// A: K-major [M,K]; B: K-major [N,K]; C row-major [M,ldc].
// 128x128x32 tiles, double-buffered cp.async, 8 warps (4m x 2n), warp 32x64.
// grid: (N/128, M/128, batch)
// ---------------------------------------------------------------------------
template <bool BIAS_N, bool BIAS_M, bool RESID, bool RND>
__global__ __launch_bounds__(256, 1)
void mma_gemm(const float* __restrict__ A, int lda, size_t sA,
              const float* __restrict__ B, int ldb, size_t sB,
              float* __restrict__ C, int ldc, size_t sC,
              int K, float alpha,
              const float* __restrict__ bias,
              const float* __restrict__ resid, size_t sR)
{
    extern __shared__ char smem[];
    const uint32_t base = smem_u32(smem);

    const int tid = threadIdx.x;
    const int wid = tid >> 5;
    const int l   = tid & 31;
    const int wm  = wid & 3;     // 4 warps along M (32 rows each)
    const int wn  = wid >> 2;    // 2 warps along N (64 cols each)

    A += (size_t)blockIdx.z * sA;
    B += (size_t)blockIdx.z * sB;
    C += (size_t)blockIdx.z * sC;
    if (RESID) resid += (size_t)blockIdx.z * sR;

    const int bm = blockIdx.y * 128;
    const int bn = blockIdx.x * 128;

    // Per-lane ldmatrix geometry (rows within frag, 16B-chunk parity).
    const int rowA = (l & 7) + ((l >> 3) & 1) * 8;  // A: mats {0,1}=k0-3 rows 0-7/8-15
    const int jA   = (l >> 4) & 1;                  //    mats {2,3}=k4-7
    const int rowB = (l & 7) + ((l >> 4) & 1) * 8;  // B: mats {0,1}=n0-7 k0-3/k4-7
    const int jB   = (l >> 3) & 1;                  //    mats {2,3}=n8-15

    float acc[2][8][4];
    #pragma unroll
    for (int i = 0; i < 2; i++)
        #pragma unroll
        for (int j = 0; j < 8; j++)
            #pragma unroll
            for (int r = 0; r < 4; r++) acc[i][j][r] = 0.f;

    const int nk = K >> 5;

    // tile loader: rows of 32 floats (128B = one swizzle atom), 8 chunks/row
    auto load_tile = [&](int it, int s) {
        const uint32_t aB = base + s * 32768;
        const uint32_t bB = aB + 16384;
        const float* ag = A + (size_t)bm * lda + (it << 5);
        const float* bg = B + (size_t)bn * ldb + (it << 5);
        #pragma unroll
        for (int i = 0; i < 4; ++i) {
            const int idx = tid + (i << 8);
            const int r = idx >> 3, c = idx & 7;
            const uint32_t so = (uint32_t)(r * 128 + ((c ^ (r & 7)) << 4));
            cp_async16(aB + so, ag + (size_t)r * lda + c * 4);
            cp_async16(bB + so, bg + (size_t)r * ldb + c * 4);
        }
        asm volatile("cp.async.commit_group;" ::: "memory");
    };

    load_tile(0, 0);
    for (int it = 0; it < nk; ++it) {
        if (it + 1 < nk) {
            load_tile(it + 1, (it + 1) & 1);
            asm volatile("cp.async.wait_group 1;" ::: "memory");
        } else {
            asm volatile("cp.async.wait_group 0;" ::: "memory");
        }
        __syncthreads();

        const uint32_t aB = base + (it & 1) * 32768;
        const uint32_t bB = aB + 16384;

        #pragma unroll
        for (int ks = 0; ks < 4; ++ks) {
            uint32_t afr[2][4];
            #pragma unroll
            for (int fm = 0; fm < 2; ++fm) {
                const int row = wm * 32 + fm * 16 + rowA;
                const int ch  = (2 * ks + jA) ^ (row & 7);
                ldsm_x4(afr[fm], aB + (uint32_t)(row * 128 + (ch << 4)));
            }
            uint32_t bfr[8][2];
            #pragma unroll
            for (int f2 = 0; f2 < 4; ++f2) {
                const int row = wn * 64 + f2 * 16 + rowB;
                const int ch  = (2 * ks + jB) ^ (row & 7);
                uint32_t t[4];
                ldsm_x4(t, bB + (uint32_t)(row * 128 + (ch << 4)));
                bfr[f2 * 2][0] = t[0]; bfr[f2 * 2][1] = t[1];
                bfr[f2 * 2 + 1][0] = t[2]; bfr[f2 * 2 + 1][1] = t[3];
            }
            #pragma unroll
            for (int fm = 0; fm < 2; ++fm)
                #pragma unroll
                for (int fn = 0; fn < 8; ++fn)
                    mma_tf32(acc[fm][fn], afr[fm], bfr[fn]);
        }
        __syncthreads();
    }

    // Epilogue: c0/c1 at (row, col..col+1), c2/c3 at (row+8, ...)
    #pragma unroll
    for (int fm = 0; fm < 2; ++fm) {
        const int r0 = bm + wm * 32 + fm * 16 + (l >> 2);
        #pragma unroll
        for (int half = 0; half < 2; ++half) {
            const int m = r0 + half * 8;
            const float bmv = BIAS_M ? bias[m] : 0.f;
            #pragma unroll
            for (int fn = 0; fn < 8; ++fn) {
                const int col = bn + wn * 64 + fn * 8 + (l & 3) * 2;
                float2 o;
                o.x = acc[fm][fn][half * 2 + 0] * alpha;
                o.y = acc[fm][fn][half * 2 + 1] * alpha;
                if (BIAS_N) { o.x += bias[col]; o.y += bias[col + 1]; }
                if (BIAS_M) { o.x += bmv; o.y += bmv; }
                if (RESID) {
                    const float2 rv = *reinterpret_cast<const float2*>(
                        &resid[(size_t)m * ldc + col]);
                    o.x += rv.x; o.y += rv.y;
                }
                if (RND) { o.x = to_tf32(o.x); o.y = to_tf32(o.y); }
                *reinterpret_cast<float2*>(&C[(size_t)m * ldc + col]) = o;
            }
        }
    }
}

// ---------------------------------------------------------------------------
__global__ __launch_bounds__(256) void gn_kernel(const float* __restrict__ x,
                                                 const float* __restrict__ scale,
                                                 const float* __restrict__ bias,
                                                 float* __restrict__ hn) {
    const int b = blockIdx.x / kG;
    const int g = blockIdx.x % kG;
    const size_t base = (size_t)b * kCN + (size_t)g * kCPG * kN;
    const float4* x4 = reinterpret_cast<const float4*>(x + base);
    float4* hn4 = reinterpret_cast<float4*>(hn + base);
    const int nvec = kCPG * kN / 4;

    float s = 0.f, ss = 0.f;
    for (int i = threadIdx.x; i < nvec; i += 256) {
        float4 v = x4[i];
        s  += v.x + v.y + v.z + v.w;
        ss += v.x * v.x + v.y * v.y + v.z * v.z + v.w * v.w;
    }
    __shared__ float smS[8], smSS[8];
    #pragma unroll
    for (int o = 16; o > 0; o >>= 1) {
        s  += __shfl_xor_sync(0xffffffffu, s, o);
        ss += __shfl_xor_sync(0xffffffffu, ss, o);
    }
    if ((threadIdx.x & 31) == 0) { smS[threadIdx.x >> 5] = s; smSS[threadIdx.x >> 5] = ss; }
    __syncthreads();
    float S = 0.f, SS = 0.f;
    #pragma unroll
    for (int i = 0; i < 8; i++) { S += smS[i]; SS += smSS[i]; }
    const float invn = 1.f / (float)(kCPG * kN);
    const float mean = S * invn;
    const float var  = SS * invn - mean * mean;
    const float inv  = rsqrtf(var + 1e-6f);

    for (int i = threadIdx.x; i < nvec; i += 256) {
        const int cl = i / (kN / 4);
        const int c  = g * kCPG + cl;
        const float sc = scale[c] * inv;
        const float bi = bias[c] - mean * sc;
        float4 v = x4[i];
        float4 r;
        r.x = v.x * sc + bi; r.y = v.y * sc + bi;
        r.z = v.z * sc + bi; r.w = v.w * sc + bi;
        hn4[i] = r;
    }
}

__global__ __launch_bounds__(256) void transpose_kernel(const float* __restrict__ src,
                                                        float* __restrict__ dst) {
    __shared__ float t[32][33];
    const size_t boff = (size_t)blockIdx.z * kCN;
    const int n0 = blockIdx.x * 32, c0 = blockIdx.y * 32;
    const int tx = threadIdx.x & 31, ty = threadIdx.x >> 5;
    #pragma unroll
    for (int i = 0; i < 4; i++)
        t[ty + i * 8][tx] = src[boff + (size_t)(c0 + ty + i * 8) * kN + n0 + tx];
    __syncthreads();
    #pragma unroll
    for (int i = 0; i < 4; i++)
        dst[boff + (size_t)(n0 + ty + i * 8) * kC + c0 + tx] = to_tf32(t[tx][ty + i * 8]);
}

__global__ __launch_bounds__(256) void round_kernel(const float* __restrict__ src,
                                                    float* __restrict__ dst, int n) {
    const int i = blockIdx.x * 256 + threadIdx.x;
    if (i < n) dst[i] = to_tf32(src[i]);
}

__global__ __launch_bounds__(256) void softmax_kernel(float* __restrict__ s) {
    float* row = s + ((size_t)blockIdx.y * kN + (size_t)blockIdx.x) * kN;
    float4* row4 = reinterpret_cast<float4*>(row);
    float4 r[4];
    float mx = -3.402823e38f;
    #pragma unroll
    for (int i = 0; i < 4; i++) {
        r[i] = row4[threadIdx.x + i * 256];
        mx = fmaxf(mx, fmaxf(fmaxf(r[i].x, r[i].y), fmaxf(r[i].z, r[i].w)));
    }
    __shared__ float sm[8];
    #pragma unroll
    for (int o = 16; o > 0; o >>= 1)
        mx = fmaxf(mx, __shfl_xor_sync(0xffffffffu, mx, o));
    if ((threadIdx.x & 31) == 0) sm[threadIdx.x >> 5] = mx;
    __syncthreads();
    float m = sm[0];
    #pragma unroll
    for (int i = 1; i < 8; i++) m = fmaxf(m, sm[i]);
    __syncthreads();
    float sum = 0.f;
    #pragma unroll
    for (int i = 0; i < 4; i++) {
        r[i].x = __expf(r[i].x - m); sum += r[i].x;
        r[i].y = __expf(r[i].y - m); sum += r[i].y;
        r[i].z = __expf(r[i].z - m); sum += r[i].z;
        r[i].w = __expf(r[i].w - m); sum += r[i].w;
    }
    #pragma unroll
    for (int o = 16; o > 0; o >>= 1)
        sum += __shfl_xor_sync(0xffffffffu, sum, o);
    if ((threadIdx.x & 31) == 0) sm[threadIdx.x >> 5] = sum;
    __syncthreads();
    float tot = 0.f;
    #pragma unroll
    for (int i = 0; i < 8; i++) tot += sm[i];
    const float inv = 1.f / tot;
    #pragma unroll
    for (int i = 0; i < 4; i++) {
        r[i].x = to_tf32(r[i].x * inv); r[i].y = to_tf32(r[i].y * inv);
        r[i].z = to_tf32(r[i].z * inv); r[i].w = to_tf32(r[i].w * inv);
        row4[threadIdx.x + i * 256] = r[i];
    }
}

// ---------------------------------------------------------------------------
extern "C" void kernel_launch(void* const* d_in, const int* in_sizes, int n_in,
                              void* d_out, int out_size) {
    const float* x  = (const float*)d_in[0];
    const float* gs = (const float*)d_in[1];
    const float* gb = (const float*)d_in[2];
    const float* wq = (const float*)d_in[3];
    const float* bq = (const float*)d_in[4];
    const float* wk = (const float*)d_in[5];
    const float* bk = (const float*)d_in[6];
    const float* wv = (const float*)d_in[7];
    const float* bv = (const float*)d_in[8];
    const float* wo = (const float*)d_in[9];
    const float* bo = (const float*)d_in[10];
    float* out = (float*)d_out;

    float *hn, *hnT, *qT, *kT, *v, *oT, *s, *wr;
    cudaGetSymbolAddress((void**)&hn,  g_hn);
    cudaGetSymbolAddress((void**)&hnT, g_hnT);
    cudaGetSymbolAddress((void**)&qT,  g_qT);
    cudaGetSymbolAddress((void**)&kT,  g_kT);
    cudaGetSymbolAddress((void**)&v,   g_v);
    cudaGetSymbolAddress((void**)&oT,  g_oT);
    cudaGetSymbolAddress((void**)&s,   g_s);
    cudaGetSymbolAddress((void**)&wr,  g_wr);
    float* wqr = wr;
    float* wkr = wr + (size_t)kC * kC;
    float* wvr = wr + 2 * (size_t)kC * kC;
    float* wor = wr + 3 * (size_t)kC * kC;

    cudaFuncSetAttribute((const void*)mma_gemm<true,  false, false, true>,
                         cudaFuncAttributeMaxDynamicSharedMemorySize, kSmemBytes);
    cudaFuncSetAttribute((const void*)mma_gemm<false, true,  false, true>,
                         cudaFuncAttributeMaxDynamicSharedMemorySize, kSmemBytes);
    cudaFuncSetAttribute((const void*)mma_gemm<false, false, false, false>,
                         cudaFuncAttributeMaxDynamicSharedMemorySize, kSmemBytes);
    cudaFuncSetAttribute((const void*)mma_gemm<false, false, false, true>,
                         cudaFuncAttributeMaxDynamicSharedMemorySize, kSmemBytes);
    cudaFuncSetAttribute((const void*)mma_gemm<false, true,  true,  false>,
                         cudaFuncAttributeMaxDynamicSharedMemorySize, kSmemBytes);

    const int ww = kC * kC;
    round_kernel<<<(ww + 255) / 256, 256>>>(wq, wqr, ww);
    round_kernel<<<(ww + 255) / 256, 256>>>(wk, wkr, ww);
    round_kernel<<<(ww + 255) / 256, 256>>>(wv, wvr, ww);
    round_kernel<<<(ww + 255) / 256, 256>>>(wo, wor, ww);

    gn_kernel<<<kB * kG, 256>>>(x, gs, gb, hn);
    transpose_kernel<<<dim3(kN / 32, kC / 32, kB), 256>>>(hn, hnT);

    // Q,K: [spatial, c] = hn_T @ W^T + b   (bias over N=out channel)
    const dim3 gQK(kC / 128, kN / 128, kB);
    mma_gemm<true, false, false, true><<<gQK, 256, kSmemBytes>>>(
        hnT, kC, kCN, wqr, kC, 0, qT, kC, kCN, kC, 1.f, bq, nullptr, 0);
    mma_gemm<true, false, false, true><<<gQK, 256, kSmemBytes>>>(
        hnT, kC, kCN, wkr, kC, 0, kT, kC, kCN, kC, 1.f, bk, nullptr, 0);

    // V: [c, spatial]   (bias over M=channel)
    const dim3 gV(kN / 128, kC / 128, kB);
    mma_gemm<false, true, false, true><<<gV, 256, kSmemBytes>>>(
        wvr, kC, 0, hnT, kC, kCN, v, kN, kCN, kC, 1.f, bv, nullptr, 0);

    // scores[i,j] = (q_t[i,:] . k_t[j,:]) / sqrt(C)
    const dim3 gS(kN / 128, kN / 128, kB);
    mma_gemm<false, false, false, false><<<gS, 256, kSmemBytes>>>(
        qT, kC, kCN, kT, kC, kCN, s, kN, kNN, kC,
        0.044194173824159216f, nullptr, nullptr, 0);

    softmax_kernel<<<dim3(kN, kB), 256>>>(s);

    // oT[i,c] = sum_j P[i,j] * v[c,j]
    mma_gemm<false, false, false, true><<<gQK, 256, kSmemBytes>>>(
        s, kN, kNN, v, kN, kCN, oT, kC, kCN, kN, 1.f, nullptr, nullptr, 0);

    // out[o,n] = W_o @ oT^T + bo + x
    mma_gemm<false, true, true, false><<<gV, 256, kSmemBytes>>>(
        wor, kC, 0, oT, kC, kCN, out, kN, kCN, kC, 1.f, bo, x, kCN);
}

// round 7
// speedup vs baseline: 9.3745x; 2.1279x over previous
#include <cuda_runtime.h>
#include <cuda_bf16.h>
#include <cstdint>
#include <cstddef>

// ---------------------------------------------------------------------------
// SpatialSelfAttention on GB300 — bf16 mma.sync.m16n8k16 tensor-core engine.
// (tcgen05 unavailable: harness lowers through compute_103 PTX.)
// Layouts: ALL five GEMMs are K-major x K-major:
//   hn_T, q_t, k_t, oT : [n_spatial, c]   bf16
//   v                  : [c, 4096]        bf16
//   scores             : [i, 4096] fp32 -> probs bf16 in place (lda 8192)
// ---------------------------------------------------------------------------

namespace {
constexpr int kB = 8;
constexpr int kC = 512;
constexpr int kN = 4096;
constexpr int kG = 32;
constexpr int kCPG = kC / kG;
constexpr size_t kCN = (size_t)kC * kN;
constexpr size_t kNN = (size_t)kN * kN;
constexpr int kSmemBytes = 2 * 32768;   // double-buffered A+B tiles (128x64 bf16 each)
}

// Scratch
__device__ float          g_hn [kB * kCN];     // fp32 groupnorm out [c][n]
__device__ __nv_bfloat16  g_hnT[kB * kCN];     // [n][c]
__device__ __nv_bfloat16  g_qT [kB * kCN];
__device__ __nv_bfloat16  g_kT [kB * kCN];
__device__ __nv_bfloat16  g_v  [kB * kCN];
__device__ __nv_bfloat16  g_oT [kB * kCN];
__device__ float          g_s  [kB * kNN];     // fp32 scores; bf16 probs in place
__device__ __nv_bfloat16  g_wr [4 * kC * kC];

// ---------------------------------------------------------------------------
__device__ __forceinline__ uint32_t smem_u32(const void* p) {
    uint32_t a;
    asm("{ .reg .u64 t; cvta.to.shared.u64 t, %1; cvt.u32.u64 %0, t; }"
        : "=r"(a) : "l"(p));
    return a;
}
__device__ __forceinline__ void cp_async16(uint32_t dst, const void* src) {
    asm volatile("cp.async.cg.shared.global [%0], [%1], 16;"
                 :: "r"(dst), "l"(src));
}
__device__ __forceinline__ void ldsm_x4(uint32_t* r, uint32_t addr) {
    asm volatile("ldmatrix.sync.aligned.m8n8.x4.shared.b16 {%0,%1,%2,%3}, [%4];"
                 : "=r"(r[0]), "=r"(r[1]), "=r"(r[2]), "=r"(r[3]) : "r"(addr));
}
__device__ __forceinline__ void mma_bf16(float* d, const uint32_t* a,
                                         const uint32_t* b) {
    asm volatile(
        "mma.sync.aligned.m16n8k16.row.col.f32.bf16.bf16.f32 "
        "{%0,%1,%2,%3}, {%4,%5,%6,%7}, {%8,%9}, {%0,%1,%2,%3};"
        : "+f"(d[0]), "+f"(d[1]), "+f"(d[2]), "+f"(d[3])
        : "r"(a[0]), "r"(a[1]), "r"(a[2]), "r"(a[3]), "r"(b[0]), "r"(b[1]));
}

// ---------------------------------------------------------------------------
// bf16 GEMM: D[m,n] = alpha * sum_k A[m,k]*B[n,k] (+bias)(+resid)
// A: K-major [M,K] bf16; B: K-major [N,K] bf16; C row-major [M,ldc] OutT.
// 128x128x64 tiles, double-buffered cp.async, 8 warps (4m x 2n), warp 32x64.
// grid: (N/128, M/128, batch)
// ---------------------------------------------------------------------------
template <typename OutT, bool BIAS_N, bool BIAS_M, bool RESID>
__global__ __launch_bounds__(256)
void mma_gemm(const __nv_bfloat16* __restrict__ A, int lda, size_t sA,
              const __nv_bfloat16* __restrict__ B, int ldb, size_t sB,
              OutT* __restrict__ C, int ldc, size_t sC,
              int K, float alpha,
              const float* __restrict__ bias,
              const float* __restrict__ resid, size_t sR)
{
    extern __shared__ char smem[];
    const uint32_t base = smem_u32(smem);

    const int tid = threadIdx.x;
    const int wid = tid >> 5;
    const int l   = tid & 31;
    const int wm  = wid & 3;     // 4 warps along M (32 rows each)
    const int wn  = wid >> 2;    // 2 warps along N (64 cols each)

    A += (size_t)blockIdx.z * sA;
    B += (size_t)blockIdx.z * sB;
    C += (size_t)blockIdx.z * sC;
    if (RESID) resid += (size_t)blockIdx.z * sR;

    const int bm = blockIdx.y * 128;
    const int bn = blockIdx.x * 128;

    // ldmatrix lane geometry (16B chunk = 8 bf16 = k-8 slice)
    const int rowA = (l & 7) + ((l >> 3) & 1) * 8;  // mats {0,1}=k0-7 rows lo/hi
    const int jA   = (l >> 4) & 1;                  // mats {2,3}=k8-15
    const int rowB = (l & 7) + ((l >> 4) & 1) * 8;  // mats {0,1}=n0-7 k-lo/hi
    const int jB   = (l >> 3) & 1;

    float acc[2][8][4];
    #pragma unroll
    for (int i = 0; i < 2; i++)
        #pragma unroll
        for (int j = 0; j < 8; j++)
            #pragma unroll
            for (int r = 0; r < 4; r++) acc[i][j][r] = 0.f;

    const int nk = K >> 6;   // BK = 64 bf16 (128B row)

    auto load_tile = [&](int it, int s) {
        const uint32_t aB = base + s * 32768;
        const uint32_t bB = aB + 16384;
        const __nv_bfloat16* ag = A + (size_t)bm * lda + (it << 6);
        const __nv_bfloat16* bg = B + (size_t)bn * ldb + (it << 6);
        #pragma unroll
        for (int i = 0; i < 4; ++i) {
            const int idx = tid + (i << 8);
            const int r = idx >> 3, c = idx & 7;
            const uint32_t so = (uint32_t)(r * 128 + ((c ^ (r & 7)) << 4));
            cp_async16(aB + so, ag + (size_t)r * lda + c * 8);
            cp_async16(bB + so, bg + (size_t)r * ldb + c * 8);
        }
        asm volatile("cp.async.commit_group;" ::: "memory");
    };

    load_tile(0, 0);
    for (int it = 0; it < nk; ++it) {
        if (it + 1 < nk) {
            load_tile(it + 1, (it + 1) & 1);
            asm volatile("cp.async.wait_group 1;" ::: "memory");
        } else {
            asm volatile("cp.async.wait_group 0;" ::: "memory");
        }
        __syncthreads();

        const uint32_t aB = base + (it & 1) * 32768;
        const uint32_t bB = aB + 16384;

        #pragma unroll
        for (int ks = 0; ks < 4; ++ks) {     // 4 x k16 per BK=64
            uint32_t afr[2][4];
            #pragma unroll
            for (int fm = 0; fm < 2; ++fm) {
                const int row = wm * 32 + fm * 16 + rowA;
                const int ch  = (2 * ks + jA) ^ (row & 7);
                ldsm_x4(afr[fm], aB + (uint32_t)(row * 128 + (ch << 4)));
            }
            uint32_t bfr[8][2];
            #pragma unroll
            for (int f2 = 0; f2 < 4; ++f2) {
                const int row = wn * 64 + f2 * 16 + rowB;
                const int ch  = (2 * ks + jB) ^ (row & 7);
                uint32_t t[4];
                ldsm_x4(t, bB + (uint32_t)(row * 128 + (ch << 4)));
                bfr[f2 * 2][0]     = t[0]; bfr[f2 * 2][1]     = t[1];
                bfr[f2 * 2 + 1][0] = t[2]; bfr[f2 * 2 + 1][1] = t[3];
            }
            #pragma unroll
            for (int fm = 0; fm < 2; ++fm)
                #pragma unroll
                for (int fn = 0; fn < 8; ++fn)
                    mma_bf16(acc[fm][fn], afr[fm], bfr[fn]);
        }
        __syncthreads();
    }

    // Epilogue
    #pragma unroll
    for (int fm = 0; fm < 2; ++fm) {
        const int r0 = bm + wm * 32 + fm * 16 + (l >> 2);
        #pragma unroll
        for (int half = 0; half < 2; ++half) {
            const int m = r0 + half * 8;
            const float bmv = BIAS_M ? bias[m] : 0.f;
            #pragma unroll
            for (int fn = 0; fn < 8; ++fn) {
                const int col = bn + wn * 64 + fn * 8 + (l & 3) * 2;
                float2 o;
                o.x = acc[fm][fn][half * 2 + 0] * alpha;
                o.y = acc[fm][fn][half * 2 + 1] * alpha;
                if (BIAS_N) { o.x += bias[col]; o.y += bias[col + 1]; }
                if (BIAS_M) { o.x += bmv; o.y += bmv; }
                if (RESID) {
                    const float2 rv = *reinterpret_cast<const float2*>(
                        &resid[(size_t)m * ldc + col]);
                    o.x += rv.x; o.y += rv.y;
                }
                OutT* dst = &C[(size_t)m * ldc + col];
                if constexpr (sizeof(OutT) == 4) {
                    *reinterpret_cast<float2*>(dst) = o;
                } else {
                    __nv_bfloat162 h = __floats2bfloat162_rn(o.x, o.y);
                    *reinterpret_cast<__nv_bfloat162*>(dst) = h;
                }
            }
        }
    }
}

// ---------------------------------------------------------------------------
__global__ __launch_bounds__(256) void gn_kernel(const float* __restrict__ x,
                                                 const float* __restrict__ scale,
                                                 const float* __restrict__ bias,
                                                 float* __restrict__ hn) {
    const int b = blockIdx.x / kG;
    const int g = blockIdx.x % kG;
    const size_t base = (size_t)b * kCN + (size_t)g * kCPG * kN;
    const float4* x4 = reinterpret_cast<const float4*>(x + base);
    float4* hn4 = reinterpret_cast<float4*>(hn + base);
    const int nvec = kCPG * kN / 4;

    float s = 0.f, ss = 0.f;
    for (int i = threadIdx.x; i < nvec; i += 256) {
        float4 v = x4[i];
        s  += v.x + v.y + v.z + v.w;
        ss += v.x * v.x + v.y * v.y + v.z * v.z + v.w * v.w;
    }
    __shared__ float smS[8], smSS[8];
    #pragma unroll
    for (int o = 16; o > 0; o >>= 1) {
        s  += __shfl_xor_sync(0xffffffffu, s, o);
        ss += __shfl_xor_sync(0xffffffffu, ss, o);
    }
    if ((threadIdx.x & 31) == 0) { smS[threadIdx.x >> 5] = s; smSS[threadIdx.x >> 5] = ss; }
    __syncthreads();
    float S = 0.f, SS = 0.f;
    #pragma unroll
    for (int i = 0; i < 8; i++) { S += smS[i]; SS += smSS[i]; }
    const float invn = 1.f / (float)(kCPG * kN);
    const float mean = S * invn;
    const float var  = SS * invn - mean * mean;
    const float inv  = rsqrtf(var + 1e-6f);

    for (int i = threadIdx.x; i < nvec; i += 256) {
        const int cl = i / (kN / 4);
        const int c  = g * kCPG + cl;
        const float sc = scale[c] * inv;
        const float bi = bias[c] - mean * sc;
        float4 v = x4[i];
        float4 r;
        r.x = v.x * sc + bi; r.y = v.y * sc + bi;
        r.z = v.z * sc + bi; r.w = v.w * sc + bi;
        hn4[i] = r;
    }
}

// hn [c][n] fp32 -> hnT [n][c] bf16
__global__ __launch_bounds__(256) void transpose_kernel(const float* __restrict__ src,
                                                        __nv_bfloat16* __restrict__ dst) {
    __shared__ float t[32][33];
    const size_t boff = (size_t)blockIdx.z * kCN;
    const int n0 = blockIdx.x * 32, c0 = blockIdx.y * 32;
    const int tx = threadIdx.x & 31, ty = threadIdx.x >> 5;
    #pragma unroll
    for (int i = 0; i < 4; i++)
        t[ty + i * 8][tx] = src[boff + (size_t)(c0 + ty + i * 8) * kN + n0 + tx];
    __syncthreads();
    #pragma unroll
    for (int i = 0; i < 4; i++)
        dst[boff + (size_t)(n0 + ty + i * 8) * kC + c0 + tx] =
            __float2bfloat16_rn(t[tx][ty + i * 8]);
}

__global__ __launch_bounds__(256) void cvt_kernel(const float* __restrict__ src,
                                                  __nv_bfloat16* __restrict__ dst, int n) {
    const int i = blockIdx.x * 256 + threadIdx.x;
    if (i < n) dst[i] = __float2bfloat16_rn(src[i]);
}

// In-place: row of 4096 fp32 scores -> 4096 bf16 probs packed at row head.
// Safe: all gmem reads complete before first __syncthreads; writes after last.
__global__ __launch_bounds__(256) void softmax_kernel(float* __restrict__ s) {
    float* row = s + ((size_t)blockIdx.y * kN + (size_t)blockIdx.x) * kN;
    float4* row4 = reinterpret_cast<float4*>(row);
    uint2* out2 = reinterpret_cast<uint2*>(row);

    float4 r[4];
    float mx = -3.402823e38f;
    #pragma unroll
    for (int i = 0; i < 4; i++) {
        r[i] = row4[threadIdx.x + i * 256];
        mx = fmaxf(mx, fmaxf(fmaxf(r[i].x, r[i].y), fmaxf(r[i].z, r[i].w)));
    }
    __shared__ float sm[8];
    #pragma unroll
    for (int o = 16; o > 0; o >>= 1)
        mx = fmaxf(mx, __shfl_xor_sync(0xffffffffu, mx, o));
    if ((threadIdx.x & 31) == 0) sm[threadIdx.x >> 5] = mx;
    __syncthreads();
    float m = sm[0];
    #pragma unroll
    for (int i = 1; i < 8; i++) m = fmaxf(m, sm[i]);
    __syncthreads();
    float sum = 0.f;
    #pragma unroll
    for (int i = 0; i < 4; i++) {
        r[i].x = __expf(r[i].x - m); sum += r[i].x;
        r[i].y = __expf(r[i].y - m); sum += r[i].y;
        r[i].z = __expf(r[i].z - m); sum += r[i].z;
        r[i].w = __expf(r[i].w - m); sum += r[i].w;
    }
    #pragma unroll
    for (int o = 16; o > 0; o >>= 1)
        sum += __shfl_xor_sync(0xffffffffu, sum, o);
    if ((threadIdx.x & 31) == 0) sm[threadIdx.x >> 5] = sum;
    __syncthreads();
    float tot = 0.f;
    #pragma unroll
    for (int i = 0; i < 8; i++) tot += sm[i];
    const float inv = 1.f / tot;
    #pragma unroll
    for (int i = 0; i < 4; i++) {
        __nv_bfloat162 lo = __floats2bfloat162_rn(r[i].x * inv, r[i].y * inv);
        __nv_bfloat162 hi = __floats2bfloat162_rn(r[i].z * inv, r[i].w * inv);
        uint2 val;
        val.x = *reinterpret_cast<uint32_t*>(&lo);
        val.y = *reinterpret_cast<uint32_t*>(&hi);
        out2[threadIdx.x + i * 256] = val;
    }
}

// ---------------------------------------------------------------------------
extern "C" void kernel_launch(void* const* d_in, const int* in_sizes, int n_in,
                              void* d_out, int out_size) {
    const float* x  = (const float*)d_in[0];
    const float* gs = (const float*)d_in[1];
    const float* gb = (const float*)d_in[2];
    const float* wq = (const float*)d_in[3];
    const float* bq = (const float*)d_in[4];
    const float* wk = (const float*)d_in[5];
    const float* bk = (const float*)d_in[6];
    const float* wv = (const float*)d_in[7];
    const float* bv = (const float*)d_in[8];
    const float* wo = (const float*)d_in[9];
    const float* bo = (const float*)d_in[10];
    float* out = (float*)d_out;

    float *hn, *s;
    __nv_bfloat16 *hnT, *qT, *kT, *v, *oT, *wr;
    cudaGetSymbolAddress((void**)&hn,  g_hn);
    cudaGetSymbolAddress((void**)&hnT, g_hnT);
    cudaGetSymbolAddress((void**)&qT,  g_qT);
    cudaGetSymbolAddress((void**)&kT,  g_kT);
    cudaGetSymbolAddress((void**)&v,   g_v);
    cudaGetSymbolAddress((void**)&oT,  g_oT);
    cudaGetSymbolAddress((void**)&s,   g_s);
    cudaGetSymbolAddress((void**)&wr,  g_wr);
    __nv_bfloat16* wqr = wr;
    __nv_bfloat16* wkr = wr + (size_t)kC * kC;
    __nv_bfloat16* wvr = wr + 2 * (size_t)kC * kC;
    __nv_bfloat16* wor = wr + 3 * (size_t)kC * kC;

    cudaFuncSetAttribute((const void*)mma_gemm<__nv_bfloat16, true,  false, false>,
                         cudaFuncAttributeMaxDynamicSharedMemorySize, kSmemBytes);
    cudaFuncSetAttribute((const void*)mma_gemm<__nv_bfloat16, false, true,  false>,
                         cudaFuncAttributeMaxDynamicSharedMemorySize, kSmemBytes);
    cudaFuncSetAttribute((const void*)mma_gemm<float,         false, false, false>,
                         cudaFuncAttributeMaxDynamicSharedMemorySize, kSmemBytes);
    cudaFuncSetAttribute((const void*)mma_gemm<__nv_bfloat16, false, false, false>,
                         cudaFuncAttributeMaxDynamicSharedMemorySize, kSmemBytes);
    cudaFuncSetAttribute((const void*)mma_gemm<float,         false, true,  true>,
                         cudaFuncAttributeMaxDynamicSharedMemorySize, kSmemBytes);

    const int ww = kC * kC;
    cvt_kernel<<<(ww + 255) / 256, 256>>>(wq, wqr, ww);
    cvt_kernel<<<(ww + 255) / 256, 256>>>(wk, wkr, ww);
    cvt_kernel<<<(ww + 255) / 256, 256>>>(wv, wvr, ww);
    cvt_kernel<<<(ww + 255) / 256, 256>>>(wo, wor, ww);

    gn_kernel<<<kB * kG, 256>>>(x, gs, gb, hn);
    transpose_kernel<<<dim3(kN / 32, kC / 32, kB), 256>>>(hn, hnT);

    // Q,K: [spatial, c] = hn_T @ W^T + b   (bias over out channel = col)
    const dim3 gQK(kC / 128, kN / 128, kB);
    mma_gemm<__nv_bfloat16, true, false, false><<<gQK, 256, kSmemBytes>>>(
        hnT, kC, kCN, wqr, kC, 0, qT, kC, kCN, kC, 1.f, bq, nullptr, 0);
    mma_gemm<__nv_bfloat16, true, false, false><<<gQK, 256, kSmemBytes>>>(
        hnT, kC, kCN, wkr, kC, 0, kT, kC, kCN, kC, 1.f, bk, nullptr, 0);

    // V: [c, spatial]   (bias over channel = row)
    const dim3 gV(kN / 128, kC / 128, kB);
    mma_gemm<__nv_bfloat16, false, true, false><<<gV, 256, kSmemBytes>>>(
        wvr, kC, 0, hnT, kC, kCN, v, kN, kCN, kC, 1.f, bv, nullptr, 0);

    // scores[i,j] = (q_t[i,:] . k_t[j,:]) / sqrt(C)  -> fp32
    const dim3 gS(kN / 128, kN / 128, kB);
    mma_gemm<float, false, false, false><<<gS, 256, kSmemBytes>>>(
        qT, kC, kCN, kT, kC, kCN, s, kN, kNN, kC,
        0.044194173824159216f, nullptr, nullptr, 0);

    // softmax: fp32 scores -> bf16 probs in place (bf16 lda = 8192)
    softmax_kernel<<<dim3(kN, kB), 256>>>(s);

    // oT[i,c] = sum_j P[i,j] * v[c,j]
    const __nv_bfloat16* probs = reinterpret_cast<const __nv_bfloat16*>(s);
    mma_gemm<__nv_bfloat16, false, false, false><<<gQK, 256, kSmemBytes>>>(
        probs, 2 * kN, 2 * kNN, v, kN, kCN, oT, kC, kCN, kN, 1.f, nullptr, nullptr, 0);

    // out[o,n] = W_o @ oT^T + bo + x
    mma_gemm<float, false, true, true><<<gV, 256, kSmemBytes>>>(
        wor, kC, 0, oT, kC, kCN, out, kN, kCN, kC, 1.f, bo, x, kCN);
}